// round 15
// baseline (speedup 1.0000x reference)
#include <cuda_runtime.h>
#include <cuda_fp16.h>
#include <cuda_bf16.h>

#define N_MAX   100000
#define E_TOT_MAX 1700000
#define IN_F    128
#define HID     64
#define NCLS    16

// ---------------- scratch (device globals; zero-initialized at load) ------
__device__ float g_h1f[N_MAX * HID];    // x @ W1, fp32 (agg1 reads full rows)
__device__ float g_hid[N_MAX * HID];
__device__ float g_h2 [N_MAX * NCLS];
__device__ float g_es1[N_MAX], g_ed1[N_MAX];
__device__ float g_es2[N_MAX], g_ed2[N_MAX];
__device__ int   g_deg[N_MAX];          // INVARIANT: all-zero at kernel_launch entry
__device__ int   g_cur[N_MAX];
__device__ int   g_rowptr[N_MAX + 1];
__device__ int2  g_edge[E_TOT_MAX];     // {src, bitcast(wt1)} per CSR slot
__device__ int   g_part[512];           // INVARIANT: all-zero at k_scan entry

// ---------------- helpers ----------------
__device__ __forceinline__ int warpSumI(int v) {
    #pragma unroll
    for (int o = 16; o; o >>= 1) v += __shfl_xor_sync(0xffffffffu, v, o);
    return v;
}
__device__ __forceinline__ unsigned long long pk2(float v) {
    unsigned long long r;
    asm("mov.b64 %0, {%1, %1};" : "=l"(r) : "f"(v));
    return r;
}
__device__ __forceinline__ unsigned long long fma2(unsigned long long a,
                                                   unsigned long long b,
                                                   unsigned long long c) {
    unsigned long long d;
    asm("fma.rn.f32x2 %0, %1, %2, %3;" : "=l"(d) : "l"(a), "l"(b), "l"(c));
    return d;
}
__device__ __forceinline__ float2 upk(unsigned long long p) {
    float2 f;
    asm("mov.b64 {%0, %1}, %2;" : "=f"(f.x), "=f"(f.y) : "l"(p));
    return f;
}
__device__ __forceinline__ float edge_wt1(int src, int dst) {
    float e = g_es1[src] + g_ed1[dst];
    e = (e >= 0.f) ? e : 0.2f * e;
    return __expf(e);
}

// ---------------- kernels ----------------
// GEMM1 (fused es1/ed1 + HISTOGRAM): h1 = x @ W1, fp32 out.
__global__ void k_gemm1(const float* __restrict__ x, const float* __restrict__ W1,
                        const float* __restrict__ as1, const float* __restrict__ ad1,
                        const int* __restrict__ ei, int E, int n) {
    for (int e = blockIdx.x * blockDim.x + threadIdx.x; e < E;
         e += gridDim.x * blockDim.x)
        atomicAdd(&g_deg[ei[E + e]], 1);

    __shared__ float xs[64][33];
    __shared__ float ws[32][64];
    __shared__ float esr[64][17];
    __shared__ float edr[64][17];
    int t = threadIdx.x;
    int br = blockIdx.x * 64;
    int tr = t >> 4, tc = t & 15;
    int r0 = tr * 4, c0 = tc * 4;
    unsigned long long accp[4][2] = {};
    for (int kc = 0; kc < IN_F; kc += 32) {
        #pragma unroll
        for (int i4 = t; i4 < 512; i4 += 256) {
            int r = i4 >> 3, q = i4 & 7;
            int gr = br + r;
            float4 v = make_float4(0.f, 0.f, 0.f, 0.f);
            if (gr < n) v = *(const float4*)(x + (size_t)gr * IN_F + kc + q * 4);
            xs[r][q * 4 + 0] = v.x; xs[r][q * 4 + 1] = v.y;
            xs[r][q * 4 + 2] = v.z; xs[r][q * 4 + 3] = v.w;
        }
        #pragma unroll
        for (int i4 = t; i4 < 512; i4 += 256)
            ((float4*)ws)[i4] = ((const float4*)(W1 + kc * HID))[i4];
        __syncthreads();
        #pragma unroll 4
        for (int k = 0; k < 32; k++) {
            unsigned long long pa0 = pk2(xs[r0 + 0][k]);
            unsigned long long pa1 = pk2(xs[r0 + 1][k]);
            unsigned long long pa2 = pk2(xs[r0 + 2][k]);
            unsigned long long pa3 = pk2(xs[r0 + 3][k]);
            const unsigned long long* wp = (const unsigned long long*)&ws[k][c0];
            unsigned long long b0 = wp[0], b1 = wp[1];
            accp[0][0] = fma2(pa0, b0, accp[0][0]); accp[0][1] = fma2(pa0, b1, accp[0][1]);
            accp[1][0] = fma2(pa1, b0, accp[1][0]); accp[1][1] = fma2(pa1, b1, accp[1][1]);
            accp[2][0] = fma2(pa2, b0, accp[2][0]); accp[2][1] = fma2(pa2, b1, accp[2][1]);
            accp[3][0] = fma2(pa3, b0, accp[3][0]); accp[3][1] = fma2(pa3, b1, accp[3][1]);
        }
        __syncthreads();
    }
    float as_l[4], ad_l[4];
    #pragma unroll
    for (int j = 0; j < 4; j++) { as_l[j] = as1[c0 + j]; ad_l[j] = ad1[c0 + j]; }
    #pragma unroll
    for (int i = 0; i < 4; i++) {
        float2 p0 = upk(accp[i][0]), p1 = upk(accp[i][1]);
        float a0 = p0.x, a1 = p0.y, a2 = p1.x, a3 = p1.y;
        int gr = br + r0 + i;
        if (gr < n)
            *(float4*)(g_h1f + (size_t)gr * HID + c0) = make_float4(a0, a1, a2, a3);
        esr[r0 + i][tc] = a0 * as_l[0] + a1 * as_l[1] + a2 * as_l[2] + a3 * as_l[3];
        edr[r0 + i][tc] = a0 * ad_l[0] + a1 * ad_l[1] + a2 * ad_l[2] + a3 * ad_l[3];
    }
    __syncthreads();
    if (t < 64) {
        int gr = br + t;
        if (gr < n) {
            float es = 0.f, ed = 0.f;
            #pragma unroll
            for (int c = 0; c < 16; c++) { es += esr[t][c]; ed += edr[t][c]; }
            g_es1[gr] = es; g_ed1[gr] = ed;
        }
    }
}

// single-pass scan: rowptr, self-loop edge (with wt1), cursor seed.
__global__ void k_scan(int n) {
    __shared__ int s[1024];
    __shared__ int warpsums[32];
    __shared__ int s_pred;
    int t = threadIdx.x, blk = blockIdx.x;
    int i = blk * 1024 + t;
    int v = 0;
    if (i < n) { v = g_deg[i] + 1; g_deg[i] = 0; }   // self-loop; self-clean for replay
    s[t] = v;
    #pragma unroll
    for (int off = 1; off < 1024; off <<= 1) {
        __syncthreads();
        int add = (t >= off) ? s[t - off] : 0;
        __syncthreads();
        s[t] += add;
    }
    __syncthreads();
    if (t == 0) *((volatile int*)&g_part[blk]) = s[1023] + 1;
    int pv = 0;
    if (t < blk) {
        volatile int* pf = (volatile int*)&g_part[t];
        int xv;
        while ((xv = *pf) == 0) { }
        pv = xv - 1;
    }
    int wsum = warpSumI(pv);
    if ((t & 31) == 0) warpsums[t >> 5] = wsum;
    __syncthreads();
    if (t < 32) {
        int x2 = warpsums[t];
        x2 = warpSumI(x2);
        if (t == 0) s_pred = x2;
    }
    __syncthreads();
    int off = s_pred;
    if (i < n) {
        int vv = s[t] + off;
        g_rowptr[i + 1] = vv;
        if (i + 1 < n) {
            g_edge[vv] = make_int2(i + 1, __float_as_int(edge_wt1(i + 1, i + 1)));
            g_cur[i + 1] = vv + 1;
        }
    }
    if (i == 0) {
        g_rowptr[0] = 0;
        g_edge[0] = make_int2(0, __float_as_int(edge_wt1(0, 0)));
        g_cur[0] = 1;
    }
}

// scatter + wt1 precompute, 2 edges/thread; block 0 re-zeros g_part for replay
__global__ void k_scatter(const int* __restrict__ ei, int E) {
    if (blockIdx.x == 0 && threadIdx.x < 512) g_part[threadIdx.x] = 0;
    int idx = blockIdx.x * blockDim.x + threadIdx.x;
    int Eh = E >> 1;
    if (idx < Eh) {
        int2 sv = ((const int2*)ei)[idx];
        int2 dv = ((const int2*)(ei + E))[idx];
        float w0 = edge_wt1(sv.x, dv.x);
        float w1 = edge_wt1(sv.y, dv.y);
        int p0 = atomicAdd(&g_cur[dv.x], 1);
        g_edge[p0] = make_int2(sv.x, __float_as_int(w0));
        int p1 = atomicAdd(&g_cur[dv.y], 1);
        g_edge[p1] = make_int2(sv.y, __float_as_int(w1));
    }
    if ((E & 1) && idx == Eh) {
        int src = ei[E - 1], dst = ei[E + E - 1];
        float w = edge_wt1(src, dst);
        int pos = atomicAdd(&g_cur[dst], 1);
        g_edge[pos] = make_int2(src, __float_as_int(w));
    }
}

// agg1: warp per dst, quarter-warp per edge; fp32 rows, precomputed weights.
// Lane fl8 owns features [4*fl8..+4) and [32+4*fl8..+4).
__global__ void k_agg1(const float* __restrict__ b1, int n) {
    int w = (blockIdx.x * blockDim.x + threadIdx.x) >> 5;
    int lane = threadIdx.x & 31;
    if (w >= n) return;
    int beg = g_rowptr[w];
    int deg = g_rowptr[w + 1] - beg;
    int q = lane >> 3, fl8 = lane & 7;
    float z = 0.f;
    float acc[8] = {};
    const int2* ep = g_edge + beg;
    #pragma unroll 2
    for (int j = q; j < deg; j += 4) {
        int2 ev = ep[j];                     // broadcast within quarter
        float wt = __int_as_float(ev.y);
        z += wt;
        const float4* hp = (const float4*)(g_h1f + (size_t)ev.x * HID);
        float4 h0 = hp[fl8];
        float4 h1 = hp[fl8 + 8];
        acc[0] += wt * h0.x; acc[1] += wt * h0.y; acc[2] += wt * h0.z; acc[3] += wt * h0.w;
        acc[4] += wt * h1.x; acc[5] += wt * h1.y; acc[6] += wt * h1.z; acc[7] += wt * h1.w;
    }
    z += __shfl_xor_sync(0xffffffffu, z, 8);
    z += __shfl_xor_sync(0xffffffffu, z, 16);
    #pragma unroll
    for (int i = 0; i < 8; i++) acc[i] += __shfl_xor_sync(0xffffffffu, acc[i], 8);
    #pragma unroll
    for (int i = 0; i < 8; i++) acc[i] += __shfl_xor_sync(0xffffffffu, acc[i], 16);
    if (q == 0) {
        float inv = 1.f / z;
        const float4* b4 = (const float4*)b1;
        float4 ba = b4[fl8], bbv = b4[fl8 + 8];
        float4 o0, o1;
        o0.x = fmaxf(acc[0] * inv + ba.x, 0.f);
        o0.y = fmaxf(acc[1] * inv + ba.y, 0.f);
        o0.z = fmaxf(acc[2] * inv + ba.z, 0.f);
        o0.w = fmaxf(acc[3] * inv + ba.w, 0.f);
        o1.x = fmaxf(acc[4] * inv + bbv.x, 0.f);
        o1.y = fmaxf(acc[5] * inv + bbv.y, 0.f);
        o1.z = fmaxf(acc[6] * inv + bbv.z, 0.f);
        o1.w = fmaxf(acc[7] * inv + bbv.w, 0.f);
        float4* hp = (float4*)(g_hid + (size_t)w * HID);
        hp[fl8] = o0;
        hp[fl8 + 8] = o1;
    }
}

// GEMM2 (fused es2/ed2): thread per node, packed f32x2
__global__ void k_gemm2(const float* __restrict__ W2, const float* __restrict__ as2,
                        const float* __restrict__ ad2, int n) {
    __shared__ float ws2[64][16];
    __shared__ float s_as[16], s_ad[16];
    int t = threadIdx.x;
    if (t < 256) ((float4*)ws2)[t] = ((const float4*)W2)[t];
    if (t < 16) { s_as[t] = as2[t]; s_ad[t] = ad2[t]; }
    __syncthreads();
    int nidx = blockIdx.x * blockDim.x + t;
    if (nidx >= n) return;
    unsigned long long accp[8] = {};
    const float4* row = (const float4*)(g_hid + (size_t)nidx * HID);
    #pragma unroll
    for (int k4 = 0; k4 < 16; k4++) {
        float4 h = row[k4];
        float hv[4] = {h.x, h.y, h.z, h.w};
        #pragma unroll
        for (int kk = 0; kk < 4; kk++) {
            int k = k4 * 4 + kk;
            unsigned long long pv = pk2(hv[kk]);
            const unsigned long long* wp = (const unsigned long long*)&ws2[k][0];
            #pragma unroll
            for (int p = 0; p < 8; p++) accp[p] = fma2(pv, wp[p], accp[p]);
        }
    }
    float a[16];
    #pragma unroll
    for (int p = 0; p < 8; p++) { float2 u = upk(accp[p]); a[2 * p] = u.x; a[2 * p + 1] = u.y; }
    float es = 0.f, ed = 0.f;
    #pragma unroll
    for (int j = 0; j < 16; j++) { es += a[j] * s_as[j]; ed += a[j] * s_ad[j]; }
    float4* outp = (float4*)(g_h2 + (size_t)nidx * NCLS);
    outp[0] = make_float4(a[0],  a[1],  a[2],  a[3]);
    outp[1] = make_float4(a[4],  a[5],  a[6],  a[7]);
    outp[2] = make_float4(a[8],  a[9],  a[10], a[11]);
    outp[3] = make_float4(a[12], a[13], a[14], a[15]);
    g_es2[nidx] = es; g_ed2[nidx] = ed;
}

// agg2: warp per dst, QUARTER-warp per edge; lane owns 2 classes (float2).
// Single-pass (no max subtraction), then log_softmax across lanes 0..7.
__global__ void k_agg2(const float* __restrict__ b2, float* __restrict__ out, int n) {
    int node = (blockIdx.x * blockDim.x + threadIdx.x) >> 5;
    int lane = threadIdx.x & 31;
    if (node >= n) return;
    int beg = g_rowptr[node];
    int deg = g_rowptr[node + 1] - beg;
    float ed = g_ed2[node];
    int q = lane >> 3, fl8 = lane & 7;
    float z = 0.f, a0 = 0.f, a1 = 0.f;
    const int2* ep = g_edge + beg;
    #pragma unroll 2
    for (int j = q; j < deg; j += 4) {
        int s = ep[j].x;                     // broadcast within quarter
        float e = g_es2[s] + ed;             // broadcast
        e = (e >= 0.f) ? e : 0.2f * e;
        float wt = __expf(e);
        z += wt;
        float2 h = ((const float2*)(g_h2 + (size_t)s * NCLS))[fl8];
        a0 += wt * h.x; a1 += wt * h.y;
    }
    z  += __shfl_xor_sync(0xffffffffu, z, 8);
    z  += __shfl_xor_sync(0xffffffffu, z, 16);
    a0 += __shfl_xor_sync(0xffffffffu, a0, 8);
    a0 += __shfl_xor_sync(0xffffffffu, a0, 16);
    a1 += __shfl_xor_sync(0xffffffffu, a1, 8);
    a1 += __shfl_xor_sync(0xffffffffu, a1, 16);
    float inv = 1.f / z;
    float2 bb = ((const float2*)b2)[fl8];
    float v0 = a0 * inv + bb.x;
    float v1 = a1 * inv + bb.y;
    // log_softmax over 16 classes spread as 2/lane across lanes 0..7 (replicated per quarter)
    float mx = fmaxf(v0, v1);
    #pragma unroll
    for (int o = 4; o; o >>= 1) mx = fmaxf(mx, __shfl_xor_sync(0xffffffffu, mx, o));
    float se = __expf(v0 - mx) + __expf(v1 - mx);
    #pragma unroll
    for (int o = 4; o; o >>= 1) se += __shfl_xor_sync(0xffffffffu, se, o);
    float ls = mx + logf(se);
    if (q == 0)
        ((float2*)(out + (size_t)node * NCLS))[fl8] = make_float2(v0 - ls, v1 - ls);
}

// ---------------- launch (single stream, graph-capture safe) ----------------
extern "C" void kernel_launch(void* const* d_in, const int* in_sizes, int n_in,
                              void* d_out, int out_size) {
    const float* x   = (const float*)d_in[0];
    const int*   ei  = (const int*)d_in[1];
    const float* W1  = (const float*)d_in[2];
    const float* as1 = (const float*)d_in[3];
    const float* ad1 = (const float*)d_in[4];
    const float* b1  = (const float*)d_in[5];
    const float* W2  = (const float*)d_in[6];
    const float* as2 = (const float*)d_in[7];
    const float* ad2 = (const float*)d_in[8];
    const float* b2  = (const float*)d_in[9];
    float* out = (float*)d_out;

    int N  = in_sizes[0] / IN_F;
    int E  = in_sizes[1] / 2;
    int nsb = (N + 1023) / 1024;
    int Eh = (E >> 1) + 1;

    k_gemm1  <<<(N + 63) / 64, 256>>>(x, W1, as1, ad1, ei, E, N);
    k_scan   <<<nsb, 1024>>>(N);
    k_scatter<<<(Eh + 255) / 256, 256>>>(ei, E);
    k_agg1   <<<(N + 7) / 8, 256>>>(b1, N);
    k_gemm2  <<<(N + 255) / 256, 256>>>(W2, as2, ad2, N);
    k_agg2   <<<(N + 7) / 8, 256>>>(b2, out, N);
}

// round 16
// speedup vs baseline: 1.1125x; 1.1125x over previous
#include <cuda_runtime.h>
#include <cuda_fp16.h>
#include <cuda_bf16.h>

#define N_MAX   100000
#define E_TOT_MAX 1700000
#define IN_F    128
#define HID     64
#define NCLS    16

// ---------------- scratch (device globals; zero-initialized at load) ------
__device__ unsigned int g_h1b[N_MAX * 32];  // x @ W1, bf16 pairs packed in uint
__device__ float g_hid[N_MAX * HID];
__device__ float g_h2 [N_MAX * NCLS];
__device__ float g_es1[N_MAX], g_ed1[N_MAX];
__device__ float g_es2[N_MAX], g_ed2[N_MAX];
__device__ int   g_deg[N_MAX];          // INVARIANT: all-zero at kernel_launch entry
__device__ int   g_cur[N_MAX];
__device__ int   g_rowptr[N_MAX + 1];
__device__ int   g_srcs[E_TOT_MAX];
__device__ int   g_part[512];           // INVARIANT: all-zero at k_scan entry

// ---------------- helpers ----------------
__device__ __forceinline__ int warpSumI(int v) {
    #pragma unroll
    for (int o = 16; o; o >>= 1) v += __shfl_xor_sync(0xffffffffu, v, o);
    return v;
}
__device__ __forceinline__ unsigned long long pk2(float v) {
    unsigned long long r;
    asm("mov.b64 %0, {%1, %1};" : "=l"(r) : "f"(v));
    return r;
}
__device__ __forceinline__ unsigned long long fma2(unsigned long long a,
                                                   unsigned long long b,
                                                   unsigned long long c) {
    unsigned long long d;
    asm("fma.rn.f32x2 %0, %1, %2, %3;" : "=l"(d) : "l"(a), "l"(b), "l"(c));
    return d;
}
__device__ __forceinline__ float2 upk(unsigned long long p) {
    float2 f;
    asm("mov.b64 {%0, %1}, %2;" : "=f"(f.x), "=f"(f.y) : "l"(p));
    return f;
}
// bf16 pair unpack via ALU (no F2F): lo = v<<16, hi = v & 0xffff0000
__device__ __forceinline__ float bflo(unsigned int v) {
    return __int_as_float((int)(v << 16));
}
__device__ __forceinline__ float bfhi(unsigned int v) {
    return __int_as_float((int)(v & 0xffff0000u));
}

// ---------------- kernels ----------------
// GEMM1 (fused es1/ed1 + HISTOGRAM): h1 = x @ W1 stored bf16.
__global__ void k_gemm1(const float* __restrict__ x, const float* __restrict__ W1,
                        const float* __restrict__ as1, const float* __restrict__ ad1,
                        const int* __restrict__ ei, int E, int n) {
    for (int e = blockIdx.x * blockDim.x + threadIdx.x; e < E;
         e += gridDim.x * blockDim.x)
        atomicAdd(&g_deg[ei[E + e]], 1);

    __shared__ float xs[64][33];
    __shared__ float ws[32][64];
    __shared__ float esr[64][17];
    __shared__ float edr[64][17];
    int t = threadIdx.x;
    int br = blockIdx.x * 64;
    int tr = t >> 4, tc = t & 15;
    int r0 = tr * 4, c0 = tc * 4;
    unsigned long long accp[4][2] = {};
    for (int kc = 0; kc < IN_F; kc += 32) {
        #pragma unroll
        for (int i4 = t; i4 < 512; i4 += 256) {
            int r = i4 >> 3, q = i4 & 7;
            int gr = br + r;
            float4 v = make_float4(0.f, 0.f, 0.f, 0.f);
            if (gr < n) v = *(const float4*)(x + (size_t)gr * IN_F + kc + q * 4);
            xs[r][q * 4 + 0] = v.x; xs[r][q * 4 + 1] = v.y;
            xs[r][q * 4 + 2] = v.z; xs[r][q * 4 + 3] = v.w;
        }
        #pragma unroll
        for (int i4 = t; i4 < 512; i4 += 256)
            ((float4*)ws)[i4] = ((const float4*)(W1 + kc * HID))[i4];
        __syncthreads();
        #pragma unroll 4
        for (int k = 0; k < 32; k++) {
            unsigned long long pa0 = pk2(xs[r0 + 0][k]);
            unsigned long long pa1 = pk2(xs[r0 + 1][k]);
            unsigned long long pa2 = pk2(xs[r0 + 2][k]);
            unsigned long long pa3 = pk2(xs[r0 + 3][k]);
            const unsigned long long* wp = (const unsigned long long*)&ws[k][c0];
            unsigned long long b0 = wp[0], b1 = wp[1];
            accp[0][0] = fma2(pa0, b0, accp[0][0]); accp[0][1] = fma2(pa0, b1, accp[0][1]);
            accp[1][0] = fma2(pa1, b0, accp[1][0]); accp[1][1] = fma2(pa1, b1, accp[1][1]);
            accp[2][0] = fma2(pa2, b0, accp[2][0]); accp[2][1] = fma2(pa2, b1, accp[2][1]);
            accp[3][0] = fma2(pa3, b0, accp[3][0]); accp[3][1] = fma2(pa3, b1, accp[3][1]);
        }
        __syncthreads();
    }
    float as_l[4], ad_l[4];
    #pragma unroll
    for (int j = 0; j < 4; j++) { as_l[j] = as1[c0 + j]; ad_l[j] = ad1[c0 + j]; }
    #pragma unroll
    for (int i = 0; i < 4; i++) {
        float2 p0 = upk(accp[i][0]), p1 = upk(accp[i][1]);
        float a0 = p0.x, a1 = p0.y, a2 = p1.x, a3 = p1.y;
        int gr = br + r0 + i;
        if (gr < n) {
            __nv_bfloat162 ba = __floats2bfloat162_rn(a0, a1);
            __nv_bfloat162 bb = __floats2bfloat162_rn(a2, a3);
            uint2 pkh;
            pkh.x = *(unsigned int*)&ba;
            pkh.y = *(unsigned int*)&bb;
            *(uint2*)(g_h1b + (size_t)gr * 32 + (c0 >> 1)) = pkh;
        }
        esr[r0 + i][tc] = a0 * as_l[0] + a1 * as_l[1] + a2 * as_l[2] + a3 * as_l[3];
        edr[r0 + i][tc] = a0 * ad_l[0] + a1 * ad_l[1] + a2 * ad_l[2] + a3 * ad_l[3];
    }
    __syncthreads();
    if (t < 64) {
        int gr = br + t;
        if (gr < n) {
            float es = 0.f, ed = 0.f;
            #pragma unroll
            for (int c = 0; c < 16; c++) { es += esr[t][c]; ed += edr[t][c]; }
            g_es1[gr] = es; g_ed1[gr] = ed;
        }
    }
}

// single-pass scan (decoupled aggregates): rowptr, self-loops, cursor seed.
__global__ void k_scan(int n) {
    __shared__ int s[1024];
    __shared__ int warpsums[32];
    __shared__ int s_pred;
    int t = threadIdx.x, blk = blockIdx.x;
    int i = blk * 1024 + t;
    int v = 0;
    if (i < n) { v = g_deg[i] + 1; g_deg[i] = 0; }   // self-loop; self-clean for replay
    s[t] = v;
    #pragma unroll
    for (int off = 1; off < 1024; off <<= 1) {
        __syncthreads();
        int add = (t >= off) ? s[t - off] : 0;
        __syncthreads();
        s[t] += add;
    }
    __syncthreads();
    if (t == 0) *((volatile int*)&g_part[blk]) = s[1023] + 1;
    int pv = 0;
    if (t < blk) {
        volatile int* pf = (volatile int*)&g_part[t];
        int xv;
        while ((xv = *pf) == 0) { }
        pv = xv - 1;
    }
    int wsum = warpSumI(pv);
    if ((t & 31) == 0) warpsums[t >> 5] = wsum;
    __syncthreads();
    if (t < 32) {
        int x2 = warpsums[t];
        x2 = warpSumI(x2);
        if (t == 0) s_pred = x2;
    }
    __syncthreads();
    int off = s_pred;
    if (i < n) {
        int vv = s[t] + off;
        g_rowptr[i + 1] = vv;
        if (i + 1 < n) { g_srcs[vv] = i + 1; g_cur[i + 1] = vv + 1; }
    }
    if (i == 0) { g_rowptr[0] = 0; g_srcs[0] = 0; g_cur[0] = 1; }
}

// scatter, 2 edges/thread via int2; block 0 re-zeros g_part for next replay
__global__ void k_scatter(const int* __restrict__ ei, int E) {
    if (blockIdx.x == 0 && threadIdx.x < 512) g_part[threadIdx.x] = 0;
    int idx = blockIdx.x * blockDim.x + threadIdx.x;
    int Eh = E >> 1;
    if (idx < Eh) {
        int2 sv = ((const int2*)ei)[idx];
        int2 dv = ((const int2*)(ei + E))[idx];
        int p0 = atomicAdd(&g_cur[dv.x], 1);
        g_srcs[p0] = sv.x;
        int p1 = atomicAdd(&g_cur[dv.y], 1);
        g_srcs[p1] = sv.y;
    }
    if ((E & 1) && idx == Eh) {
        int src = ei[E - 1], dst = ei[E + E - 1];
        int pos = atomicAdd(&g_cur[dst], 1);
        g_srcs[pos] = src;
    }
}

// agg1 single-pass: warp per dst, quarter-warp per edge, bf16 rows (ALU unpack)
__global__ void k_agg1(const float* __restrict__ b1, int n) {
    int w = (blockIdx.x * blockDim.x + threadIdx.x) >> 5;
    int lane = threadIdx.x & 31;
    if (w >= n) return;
    int beg = g_rowptr[w];
    int deg = g_rowptr[w + 1] - beg;
    float ed = g_ed1[w];
    int q = lane >> 3, fl8 = lane & 7;
    float z = 0.f;
    float acc[8] = {};
    const int* sp = g_srcs + beg;
    #pragma unroll 2
    for (int j = q; j < deg; j += 4) {
        int s = sp[j];                       // broadcast within quarter
        float e = g_es1[s] + ed;             // broadcast
        e = (e >= 0.f) ? e : 0.2f * e;
        float wt = __expf(e);
        z += wt;
        uint4 hv = ((const uint4*)(g_h1b + (size_t)s * 32))[fl8];
        acc[0] += wt * bflo(hv.x); acc[1] += wt * bfhi(hv.x);
        acc[2] += wt * bflo(hv.y); acc[3] += wt * bfhi(hv.y);
        acc[4] += wt * bflo(hv.z); acc[5] += wt * bfhi(hv.z);
        acc[6] += wt * bflo(hv.w); acc[7] += wt * bfhi(hv.w);
    }
    z += __shfl_xor_sync(0xffffffffu, z, 8);
    z += __shfl_xor_sync(0xffffffffu, z, 16);
    #pragma unroll
    for (int i = 0; i < 8; i++) acc[i] += __shfl_xor_sync(0xffffffffu, acc[i], 8);
    #pragma unroll
    for (int i = 0; i < 8; i++) acc[i] += __shfl_xor_sync(0xffffffffu, acc[i], 16);
    if (q == 0) {
        float inv = 1.f / z;
        const float4* b4 = (const float4*)b1;
        float4 ba = b4[2 * fl8], bbv = b4[2 * fl8 + 1];
        float4 o0, o1;
        o0.x = fmaxf(acc[0] * inv + ba.x, 0.f);
        o0.y = fmaxf(acc[1] * inv + ba.y, 0.f);
        o0.z = fmaxf(acc[2] * inv + ba.z, 0.f);
        o0.w = fmaxf(acc[3] * inv + ba.w, 0.f);
        o1.x = fmaxf(acc[4] * inv + bbv.x, 0.f);
        o1.y = fmaxf(acc[5] * inv + bbv.y, 0.f);
        o1.z = fmaxf(acc[6] * inv + bbv.z, 0.f);
        o1.w = fmaxf(acc[7] * inv + bbv.w, 0.f);
        float4* hp = (float4*)(g_hid + (size_t)w * HID);
        hp[2 * fl8] = o0;
        hp[2 * fl8 + 1] = o1;
    }
}

// GEMM2 (fused es2/ed2): thread per node, packed f32x2
__global__ void k_gemm2(const float* __restrict__ W2, const float* __restrict__ as2,
                        const float* __restrict__ ad2, int n) {
    __shared__ float ws2[64][16];
    __shared__ float s_as[16], s_ad[16];
    int t = threadIdx.x;
    if (t < 256) ((float4*)ws2)[t] = ((const float4*)W2)[t];
    if (t < 16) { s_as[t] = as2[t]; s_ad[t] = ad2[t]; }
    __syncthreads();
    int nidx = blockIdx.x * blockDim.x + t;
    if (nidx >= n) return;
    unsigned long long accp[8] = {};
    const float4* row = (const float4*)(g_hid + (size_t)nidx * HID);
    #pragma unroll
    for (int k4 = 0; k4 < 16; k4++) {
        float4 h = row[k4];
        float hv[4] = {h.x, h.y, h.z, h.w};
        #pragma unroll
        for (int kk = 0; kk < 4; kk++) {
            int k = k4 * 4 + kk;
            unsigned long long pv = pk2(hv[kk]);
            const unsigned long long* wp = (const unsigned long long*)&ws2[k][0];
            #pragma unroll
            for (int p = 0; p < 8; p++) accp[p] = fma2(pv, wp[p], accp[p]);
        }
    }
    float a[16];
    #pragma unroll
    for (int p = 0; p < 8; p++) { float2 u = upk(accp[p]); a[2 * p] = u.x; a[2 * p + 1] = u.y; }
    float es = 0.f, ed = 0.f;
    #pragma unroll
    for (int j = 0; j < 16; j++) { es += a[j] * s_as[j]; ed += a[j] * s_ad[j]; }
    float4* outp = (float4*)(g_h2 + (size_t)nidx * NCLS);
    outp[0] = make_float4(a[0],  a[1],  a[2],  a[3]);
    outp[1] = make_float4(a[4],  a[5],  a[6],  a[7]);
    outp[2] = make_float4(a[8],  a[9],  a[10], a[11]);
    outp[3] = make_float4(a[12], a[13], a[14], a[15]);
    g_es2[nidx] = es; g_ed2[nidx] = ed;
}

// agg2 single-pass: warp per dst, quarter-warp per edge; lane owns 2 classes
__global__ void k_agg2(const float* __restrict__ b2, float* __restrict__ out, int n) {
    int node = (blockIdx.x * blockDim.x + threadIdx.x) >> 5;
    int lane = threadIdx.x & 31;
    if (node >= n) return;
    int beg = g_rowptr[node];
    int deg = g_rowptr[node + 1] - beg;
    float ed = g_ed2[node];
    int q = lane >> 3, fl8 = lane & 7;
    float z = 0.f, a0 = 0.f, a1 = 0.f;
    const int* sp = g_srcs + beg;
    #pragma unroll 2
    for (int j = q; j < deg; j += 4) {
        int s = sp[j];                       // broadcast within quarter
        float e = g_es2[s] + ed;             // broadcast
        e = (e >= 0.f) ? e : 0.2f * e;
        float wt = __expf(e);
        z += wt;
        float2 h = ((const float2*)(g_h2 + (size_t)s * NCLS))[fl8];
        a0 += wt * h.x; a1 += wt * h.y;
    }
    z  += __shfl_xor_sync(0xffffffffu, z, 8);
    z  += __shfl_xor_sync(0xffffffffu, z, 16);
    a0 += __shfl_xor_sync(0xffffffffu, a0, 8);
    a0 += __shfl_xor_sync(0xffffffffu, a0, 16);
    a1 += __shfl_xor_sync(0xffffffffu, a1, 8);
    a1 += __shfl_xor_sync(0xffffffffu, a1, 16);
    float inv = 1.f / z;
    float2 bb = ((const float2*)b2)[fl8];
    float v0 = a0 * inv + bb.x;
    float v1 = a1 * inv + bb.y;
    // log_softmax over 16 classes (2/lane across lanes 0..7, replicated per quarter)
    float mx = fmaxf(v0, v1);
    #pragma unroll
    for (int o = 4; o; o >>= 1) mx = fmaxf(mx, __shfl_xor_sync(0xffffffffu, mx, o));
    float se = __expf(v0 - mx) + __expf(v1 - mx);
    #pragma unroll
    for (int o = 4; o; o >>= 1) se += __shfl_xor_sync(0xffffffffu, se, o);
    float ls = mx + logf(se);
    if (q == 0)
        ((float2*)(out + (size_t)node * NCLS))[fl8] = make_float2(v0 - ls, v1 - ls);
}

// ---------------- launch (single stream, graph-capture safe) ----------------
extern "C" void kernel_launch(void* const* d_in, const int* in_sizes, int n_in,
                              void* d_out, int out_size) {
    const float* x   = (const float*)d_in[0];
    const int*   ei  = (const int*)d_in[1];
    const float* W1  = (const float*)d_in[2];
    const float* as1 = (const float*)d_in[3];
    const float* ad1 = (const float*)d_in[4];
    const float* b1  = (const float*)d_in[5];
    const float* W2  = (const float*)d_in[6];
    const float* as2 = (const float*)d_in[7];
    const float* ad2 = (const float*)d_in[8];
    const float* b2  = (const float*)d_in[9];
    float* out = (float*)d_out;

    int N  = in_sizes[0] / IN_F;
    int E  = in_sizes[1] / 2;
    int nsb = (N + 1023) / 1024;
    int Eh = (E >> 1) + 1;

    k_gemm1  <<<(N + 63) / 64, 256>>>(x, W1, as1, ad1, ei, E, N);
    k_scan   <<<nsb, 1024>>>(N);
    k_scatter<<<(Eh + 255) / 256, 256>>>(ei, E);
    k_agg1   <<<(N + 7) / 8, 256>>>(b1, N);
    k_gemm2  <<<(N + 255) / 256, 256>>>(W2, as2, ad2, N);
    k_agg2   <<<(N + 7) / 8, 256>>>(b2, out, N);
}